// round 4
// baseline (speedup 1.0000x reference)
#include <cuda_runtime.h>
#include <math.h>

#define Bn 2
#define Tn 1536
#define Dn 1536
#define Hn 8
#define Kn 64
#define Vn 192
#define HK 512       // H*K
#define HV 1536      // H*V
#define Rn 3071      // 2T-1

// ---------------- scratch (device globals; no allocation allowed) -------------
__device__ float g_emb[(size_t)Rn * 192];
__device__ float g_gmax;
__device__ float g_rkT[(size_t)HK * 3072];   // [h*64+kd][m], ld 3072 (col 3071 pad)
__device__ float g_q[(size_t)Bn * Tn * HK];
__device__ float g_kT[(size_t)HK * 3072];    // [h*64+kd][b*T+t]
__device__ float g_v[(size_t)Bn * Tn * HV];  // tf32-rounded
__device__ float g_att[(size_t)Bn * Tn * HV];

// ---------------- tf32 helpers -------------------------------------------------
__device__ __forceinline__ unsigned f2tf(float x) {
    unsigned u; asm("cvt.rna.tf32.f32 %0, %1;" : "=r"(u) : "f"(x)); return u;
}
__device__ __forceinline__ void mma8(float d[4], const unsigned a[4], const unsigned b[2]) {
    asm volatile(
        "mma.sync.aligned.m16n8k8.row.col.f32.tf32.tf32.f32 "
        "{%0,%1,%2,%3}, {%4,%5,%6,%7}, {%8,%9}, {%0,%1,%2,%3};"
        : "+f"(d[0]), "+f"(d[1]), "+f"(d[2]), "+f"(d[3])
        : "r"(a[0]), "r"(a[1]), "r"(a[2]), "r"(a[3]), "r"(b[0]), "r"(b[1]));
}

// ---------------- positional features ----------------------------------------
__global__ void pos_fill() {
    int idx = blockIdx.x * 256 + threadIdx.x;
    if (idx >= Rn * 96) return;
    int p = idx / 96, c = idx % 96;
    float ap = fabsf((float)(p - (Tn - 1)));
    float v;
    if (c < 32) {
        float max_range = log2f((float)Tn);
        float hl = exp2f(3.0f + (float)c * (max_range - 3.0f) / 31.0f);
        v = exp2f(-ap / hl);
    } else if (c < 64) {
        float w = exp2f((float)(c - 32 + 1)) - 1.0f;
        v = (w > ap) ? 1.0f : 0.0f;
    } else {
        int i = c - 64;
        float mean = 48.0f * (float)(i + 1);
        float conc = (mean / 24.0f) * (mean / 24.0f);
        float rate = mean * (1.0f / 576.0f);
        float lp = (conc - 1.0f) * logf(ap) - rate * ap
                   - (lgammaf(conc) - conc * logf(rate));
        v = expf(lp) + 1e-8f;
    }
    g_emb[(size_t)p * 192 + c] = v;
}

__global__ void pos_max() {
    __shared__ float red[256];
    int tid = threadIdx.x;
    float m = 0.0f;
    for (int idx = tid; idx < Rn * 32; idx += 256) {
        int p = idx >> 5, i = idx & 31;
        m = fmaxf(m, g_emb[(size_t)p * 192 + 64 + i]);
    }
    red[tid] = m;
    __syncthreads();
    for (int o = 128; o > 0; o >>= 1) {
        if (tid < o) red[tid] = fmaxf(red[tid], red[tid + o]);
        __syncthreads();
    }
    if (tid == 0) g_gmax = red[0];
}

__global__ void pos_fin() {
    int idx = blockIdx.x * 256 + threadIdx.x;
    if (idx >= Rn * 96) return;
    int p = idx / 96, c = idx % 96;
    float v = g_emb[(size_t)p * 192 + c];
    if (c >= 64) {
        v = v / g_gmax;
        g_emb[(size_t)p * 192 + c] = v;
    }
    float sgn = (p < Tn - 1) ? -1.0f : ((p > Tn - 1) ? 1.0f : 0.0f);
    g_emb[(size_t)p * 192 + 96 + c] = sgn * v;
}

// ---------------- tf32 tensor-core GEMM: C = alpha * A @ B --------------------
// mode bit0: round output to tf32; bit1: store transposed C[c*ldc + r].
__device__ __forceinline__ float cvtmode(float x, int mode) {
    return (mode & 1) ? __uint_as_float(f2tf(x)) : x;
}
__global__ __launch_bounds__(256) void tgemm_kernel(
    const float* __restrict__ A, const float* __restrict__ B, float* __restrict__ C,
    int M, int N, int Kd, int lda, int ldb, int ldc, int Hdim,
    long sAb, long sAh, long sBb, long sBh, long sCb, long sCh, float alpha, int mode)
{
    int z = blockIdx.z;
    int bb = z / Hdim, hh = z % Hdim;
    A += (size_t)bb * sAb + (size_t)hh * sAh;
    B += (size_t)bb * sBb + (size_t)hh * sBh;
    C += (size_t)bb * sCb + (size_t)hh * sCh;

    __shared__ unsigned As[128 * 36];   // [m][k], ld 36
    __shared__ unsigned Bs[32 * 136];   // [k][n], ld 136

    int tid = threadIdx.x;
    int bm = blockIdx.y * 128, bn = blockIdx.x * 128;
    int w = tid >> 5, lane = tid & 31;
    int wm = w & 1, wn = w >> 1;
    int lr = lane >> 2, lc = lane & 3;

    int arow0 = tid >> 3;
    int ac4   = (tid & 7) << 2;
    int bc4   = lane << 2;
    bool bvalid = (bn + bc4) < N;
    bool avalid[4];
#pragma unroll
    for (int it = 0; it < 4; it++) avalid[it] = (bm + arow0 + it * 32) < M;

    float4 av[4], bv[4];
    const float4 z4 = make_float4(0.f, 0.f, 0.f, 0.f);
#pragma unroll
    for (int it = 0; it < 4; it++) {
        av[it] = avalid[it] ? *(const float4*)(A + (size_t)(bm + arow0 + it * 32) * lda + ac4) : z4;
        bv[it] = bvalid ? *(const float4*)(B + (size_t)(it * 8 + w) * ldb + bn + bc4) : z4;
    }

    float acc[4][4][4] = {};

    for (int k0 = 0; k0 < Kd; k0 += 32) {
#pragma unroll
        for (int it = 0; it < 4; it++) {
            unsigned* ap = As + (arow0 + it * 32) * 36 + ac4;
            ap[0] = f2tf(av[it].x); ap[1] = f2tf(av[it].y);
            ap[2] = f2tf(av[it].z); ap[3] = f2tf(av[it].w);
            unsigned* bp = Bs + (it * 8 + w) * 136 + bc4;
            bp[0] = f2tf(bv[it].x); bp[1] = f2tf(bv[it].y);
            bp[2] = f2tf(bv[it].z); bp[3] = f2tf(bv[it].w);
        }
        __syncthreads();
        if (k0 + 32 < Kd) {
#pragma unroll
            for (int it = 0; it < 4; it++) {
                av[it] = avalid[it] ? *(const float4*)(A + (size_t)(bm + arow0 + it * 32) * lda + (k0 + 32) + ac4) : z4;
                bv[it] = bvalid ? *(const float4*)(B + (size_t)(k0 + 32 + it * 8 + w) * ldb + bn + bc4) : z4;
            }
        }
#pragma unroll
        for (int s = 0; s < 4; s++) {
            int kb = s * 8;
            unsigned afr[4][4];
#pragma unroll
            for (int i = 0; i < 4; i++) {
                int r = wm * 64 + i * 16 + lr;
                afr[i][0] = As[r * 36 + kb + lc];
                afr[i][1] = As[(r + 8) * 36 + kb + lc];
                afr[i][2] = As[r * 36 + kb + 4 + lc];
                afr[i][3] = As[(r + 8) * 36 + kb + 4 + lc];
            }
            unsigned bfr[4][2];
#pragma unroll
            for (int j = 0; j < 4; j++) {
                int cc = wn * 32 + j * 8 + lr;
                bfr[j][0] = Bs[(kb + lc) * 136 + cc];
                bfr[j][1] = Bs[(kb + 4 + lc) * 136 + cc];
            }
#pragma unroll
            for (int i = 0; i < 4; i++)
#pragma unroll
                for (int j = 0; j < 4; j++)
                    mma8(acc[i][j], afr[i], bfr[j]);
        }
        __syncthreads();
    }

    if (mode & 2) {
        // transposed scalar store: C[c][r]
#pragma unroll
        for (int i = 0; i < 4; i++) {
            int r0 = bm + wm * 64 + i * 16 + lr;
#pragma unroll
            for (int j = 0; j < 4; j++) {
                int c0 = bn + wn * 32 + j * 8 + lc * 2;
                if (c0 < N) {
                    if (r0 < M) {
                        C[(size_t)c0 * ldc + r0]       = cvtmode(alpha * acc[i][j][0], mode);
                        C[(size_t)(c0 + 1) * ldc + r0] = cvtmode(alpha * acc[i][j][1], mode);
                    }
                    if (r0 + 8 < M) {
                        C[(size_t)c0 * ldc + r0 + 8]       = cvtmode(alpha * acc[i][j][2], mode);
                        C[(size_t)(c0 + 1) * ldc + r0 + 8] = cvtmode(alpha * acc[i][j][3], mode);
                    }
                }
            }
        }
    } else {
#pragma unroll
        for (int i = 0; i < 4; i++) {
            int r0 = bm + wm * 64 + i * 16 + lr;
#pragma unroll
            for (int j = 0; j < 4; j++) {
                int c0 = bn + wn * 32 + j * 8 + lc * 2;
                if (c0 < N) {
                    if (r0 < M)
                        *(float2*)(C + (size_t)r0 * ldc + c0) =
                            make_float2(cvtmode(alpha * acc[i][j][0], mode),
                                        cvtmode(alpha * acc[i][j][1], mode));
                    if (r0 + 8 < M)
                        *(float2*)(C + (size_t)(r0 + 8) * ldc + c0) =
                            make_float2(cvtmode(alpha * acc[i][j][2], mode),
                                        cvtmode(alpha * acc[i][j][3], mode));
                }
            }
        }
    }
}

// ---------------- fused flash attention with relative shift -------------------
// K/RK tiles in smem k-major with interleaved n-permutation n'=(n&7)*s+(n>>3)
// so B-fragments load as LDS.128; V likewise. All tiles pre-rounded tf32.
#define LDKC 104   // Kc  [kd][j'],  s=12
#define LDRK 168   // RKc [kd][m'],  s=20
#define LDVC 232   // Vc  [j][v'],   s=28
#define LDPS 68    // Ps  [q][j]  (aliases Kc)
#define LDR  132   // rel [q][m]  (aliases RKc)
__global__ __launch_bounds__(256, 1) void flash_kernel(
    const float* __restrict__ rwb, const float* __restrict__ rrb)
{
    extern __shared__ float smf[];
    float* Kc  = smf;                        // 64*LDKC
    float* RKc = Kc + 64 * LDKC;             // 64*LDRK
    float* Vc  = RKc + 64 * LDRK;            // 64*LDVC
    float* smx = Vc + 64 * LDVC;             // [128]
    float* sms = smx + 128;                  // [128]
    float* Ps  = Kc;                         // alias
    float* rel = RKc;                        // alias

    int bh = blockIdx.y, b = bh >> 3, h = bh & 7;
    int q0 = blockIdx.x * 64;
    int tid = threadIdx.x, w = tid >> 5, lane = tid & 31;
    int lr = lane >> 2, lc = lane & 3;
    int qw = (w >> 1) * 16;
    int nhalf = w & 1;

    const float* qg = g_q + (size_t)(b * Tn + q0) * HK + h * Kn;

    // Q fragments with folded biases
    unsigned qc[8][4], qr[8][4];
#pragma unroll
    for (int s = 0; s < 8; s++) {
        int c = s * 8 + lc;
        float rw0 = rwb[h * Kn + c],     rr0 = rrb[h * Kn + c];
        float rw1 = rwb[h * Kn + c + 4], rr1 = rrb[h * Kn + c + 4];
        float q00 = qg[(size_t)(qw + lr) * HK + c];
        float q10 = qg[(size_t)(qw + 8 + lr) * HK + c];
        float q01 = qg[(size_t)(qw + lr) * HK + c + 4];
        float q11 = qg[(size_t)(qw + 8 + lr) * HK + c + 4];
        qc[s][0] = f2tf(q00 + rw0); qc[s][1] = f2tf(q10 + rw0);
        qc[s][2] = f2tf(q01 + rw1); qc[s][3] = f2tf(q11 + rw1);
        qr[s][0] = f2tf(q00 + rr0); qr[s][1] = f2tf(q10 + rr0);
        qr[s][2] = f2tf(q01 + rr1); qr[s][3] = f2tf(q11 + rr1);
    }

    float accO[12][4] = {};
    float m_lo = -1e30f, m_hi = -1e30f, l_lo = 0.f, l_hi = 0.f;

    for (int jt = 0; jt < 24; jt++) {
        int j0 = jt * 64;
        __syncthreads();

        // ---- K tile [kd][j'] from g_kT ----
        const float* kg = g_kT + (size_t)(h * 64) * 3072 + b * Tn + j0;
#pragma unroll
        for (int it = 0; it < 4; it++) {
            int f = it * 256 + tid;
            int kd = f >> 4, jc4 = (f & 15) << 2;
            float4 kv = *(const float4*)(kg + (size_t)kd * 3072 + jc4);
            float* p = Kc + kd * LDKC + (jc4 & 7) * 12 + (jc4 >> 3);
            p[0] = kv.x; p[12] = kv.y; p[24] = kv.z; p[36] = kv.w;
        }
        // ---- RK band [kd][m'] from g_rkT (col 127 zeroed) ----
        int mbase = 1472 + j0 - q0;   // (T-1) + j0 - q0 - 63, in [0,2944]
        const float* rg = g_rkT + (size_t)(h * 64) * 3072 + mbase;
#pragma unroll
        for (int it = 0; it < 8; it++) {
            int f = it * 256 + tid;
            int kd = f >> 5, mc4 = (f & 31) << 2;
            float4 rv = *(const float4*)(rg + (size_t)kd * 3072 + mc4);
            float* p = RKc + kd * LDRK + (mc4 & 7) * 20 + (mc4 >> 3);
            p[0] = rv.x; p[20] = rv.y; p[40] = rv.z;
            p[60] = (mc4 == 124) ? 0.f : rv.w;
        }
        // ---- V tile [j][v'] from g_v ----
        const float* vg = g_v + (size_t)(b * Tn + j0) * HV + h * Vn;
#pragma unroll
        for (int it = 0; it < 12; it++) {
            int f = it * 256 + tid;
            int row = f / 48, vc4 = (f % 48) << 2;
            float4 vv = *(const float4*)(vg + (size_t)row * HV + vc4);
            float* p = Vc + row * LDVC + (vc4 & 7) * 28 + (vc4 >> 3);
            p[0] = vv.x; p[28] = vv.y; p[56] = vv.z; p[84] = vv.w;
        }
        __syncthreads();

        // ---- MMAs: rel (64 cols/warp) + content (32 cols/warp), LDS.128 frags ----
        float acc1[8][4] = {};
        float acc2[4][4] = {};
#pragma unroll
        for (int s = 0; s < 8; s++) {
            int kb = s * 8;
            float c0[4], c1[4];
            *(float4*)c0 = *(const float4*)&Kc[(kb + lc) * LDKC + lr * 12 + nhalf * 4];
            *(float4*)c1 = *(const float4*)&Kc[(kb + 4 + lc) * LDKC + lr * 12 + nhalf * 4];
#pragma unroll
            for (int jf = 0; jf < 4; jf++) {
                unsigned bfr[2] = { __float_as_uint(c0[jf]), __float_as_uint(c1[jf]) };
                mma8(acc2[jf], qc[s], bfr);
            }
            float r0[8], r1[8];
            *(float4*)r0       = *(const float4*)&RKc[(kb + lc) * LDRK + lr * 20 + nhalf * 8];
            *(float4*)(r0 + 4) = *(const float4*)&RKc[(kb + lc) * LDRK + lr * 20 + nhalf * 8 + 4];
            *(float4*)r1       = *(const float4*)&RKc[(kb + 4 + lc) * LDRK + lr * 20 + nhalf * 8];
            *(float4*)(r1 + 4) = *(const float4*)&RKc[(kb + 4 + lc) * LDRK + lr * 20 + nhalf * 8 + 4];
#pragma unroll
            for (int jf = 0; jf < 8; jf++) {
                unsigned bfr[2] = { __float_as_uint(r0[jf]), __float_as_uint(r1[jf]) };
                mma8(acc1[jf], qr[s], bfr);
            }
        }
        __syncthreads();   // done reading Kc/RKc -> safe to alias

        // ---- stage rel into smem (aliased over RKc) ----
#pragma unroll
        for (int jf = 0; jf < 8; jf++) {
            int ml = nhalf * 64 + jf * 8 + 2 * lc;
            *(float2*)&rel[(qw + lr) * LDR + ml]     = make_float2(acc1[jf][0], acc1[jf][1]);
            *(float2*)&rel[(qw + 8 + lr) * LDR + ml] = make_float2(acc1[jf][2], acc1[jf][3]);
        }
        __syncthreads();

        // ---- logits = content + shifted rel; row max ----
        float lg[4][4];
        float mx_lo = -1e30f, mx_hi = -1e30f;
#pragma unroll
        for (int jf = 0; jf < 4; jf++) {
            int jl = nhalf * 32 + jf * 8 + 2 * lc;
            int mlo = 63 + jl - (qw + lr);
            int mhi = mlo - 8;
            lg[jf][0] = acc2[jf][0] + rel[(qw + lr) * LDR + mlo];
            lg[jf][1] = acc2[jf][1] + rel[(qw + lr) * LDR + mlo + 1];
            lg[jf][2] = acc2[jf][2] + rel[(qw + 8 + lr) * LDR + mhi];
            lg[jf][3] = acc2[jf][3] + rel[(qw + 8 + lr) * LDR + mhi + 1];
            mx_lo = fmaxf(mx_lo, fmaxf(lg[jf][0], lg[jf][1]));
            mx_hi = fmaxf(mx_hi, fmaxf(lg[jf][2], lg[jf][3]));
        }
        mx_lo = fmaxf(mx_lo, __shfl_xor_sync(0xffffffffu, mx_lo, 1));
        mx_lo = fmaxf(mx_lo, __shfl_xor_sync(0xffffffffu, mx_lo, 2));
        mx_hi = fmaxf(mx_hi, __shfl_xor_sync(0xffffffffu, mx_hi, 1));
        mx_hi = fmaxf(mx_hi, __shfl_xor_sync(0xffffffffu, mx_hi, 2));
        if (lc == 0) {
            smx[nhalf * 64 + qw + lr] = mx_lo;
            smx[nhalf * 64 + qw + 8 + lr] = mx_hi;
        }
        __syncthreads();
        mx_lo = fmaxf(mx_lo, smx[(1 - nhalf) * 64 + qw + lr]);
        mx_hi = fmaxf(mx_hi, smx[(1 - nhalf) * 64 + qw + 8 + lr]);

        // ---- online softmax update (fast exp) ----
        float mn_lo = fmaxf(m_lo, mx_lo), mn_hi = fmaxf(m_hi, mx_hi);
        float sc_lo = __expf(m_lo - mn_lo), sc_hi = __expf(m_hi - mn_hi);
        m_lo = mn_lo; m_hi = mn_hi;
        float su_lo = 0.f, su_hi = 0.f;
        float pv[4][4];
#pragma unroll
        for (int jf = 0; jf < 4; jf++) {
            pv[jf][0] = __expf(lg[jf][0] - mn_lo);
            pv[jf][1] = __expf(lg[jf][1] - mn_lo);
            pv[jf][2] = __expf(lg[jf][2] - mn_hi);
            pv[jf][3] = __expf(lg[jf][3] - mn_hi);
            su_lo += pv[jf][0] + pv[jf][1];
            su_hi += pv[jf][2] + pv[jf][3];
        }
        su_lo += __shfl_xor_sync(0xffffffffu, su_lo, 1);
        su_lo += __shfl_xor_sync(0xffffffffu, su_lo, 2);
        su_hi += __shfl_xor_sync(0xffffffffu, su_hi, 1);
        su_hi += __shfl_xor_sync(0xffffffffu, su_hi, 2);
        if (lc == 0) {
            sms[nhalf * 64 + qw + lr] = su_lo;
            sms[nhalf * 64 + qw + 8 + lr] = su_hi;
        }
        // ---- stage P (tf32) into smem (aliased over Kc) ----
#pragma unroll
        for (int jf = 0; jf < 4; jf++) {
            int jl = nhalf * 32 + jf * 8 + 2 * lc;
            *(uint2*)&Ps[(qw + lr) * LDPS + jl] =
                make_uint2(f2tf(pv[jf][0]), f2tf(pv[jf][1]));
            *(uint2*)&Ps[(qw + 8 + lr) * LDPS + jl] =
                make_uint2(f2tf(pv[jf][2]), f2tf(pv[jf][3]));
        }
        __syncthreads();
        l_lo = l_lo * sc_lo + su_lo + sms[(1 - nhalf) * 64 + qw + lr];
        l_hi = l_hi * sc_hi + su_hi + sms[(1 - nhalf) * 64 + qw + 8 + lr];

        // ---- rescale O, then O += P @ V (LDS.128 V frags) ----
#pragma unroll
        for (int nf = 0; nf < 12; nf++) {
            accO[nf][0] *= sc_lo; accO[nf][1] *= sc_lo;
            accO[nf][2] *= sc_hi; accO[nf][3] *= sc_hi;
        }
#pragma unroll
        for (int s = 0; s < 8; s++) {
            int kb = s * 8;
            unsigned afr[4];
            afr[0] = __float_as_uint(Ps[(qw + lr) * LDPS + kb + lc]);
            afr[1] = __float_as_uint(Ps[(qw + 8 + lr) * LDPS + kb + lc]);
            afr[2] = __float_as_uint(Ps[(qw + lr) * LDPS + kb + 4 + lc]);
            afr[3] = __float_as_uint(Ps[(qw + 8 + lr) * LDPS + kb + 4 + lc]);
            float v0[12], v1[12];
            const float* vb0 = &Vc[(kb + lc) * LDVC + lr * 28 + nhalf * 12];
            const float* vb1 = &Vc[(kb + 4 + lc) * LDVC + lr * 28 + nhalf * 12];
            *(float4*)v0 = *(const float4*)vb0;
            *(float4*)(v0 + 4) = *(const float4*)(vb0 + 4);
            *(float4*)(v0 + 8) = *(const float4*)(vb0 + 8);
            *(float4*)v1 = *(const float4*)vb1;
            *(float4*)(v1 + 4) = *(const float4*)(vb1 + 4);
            *(float4*)(v1 + 8) = *(const float4*)(vb1 + 8);
#pragma unroll
            for (int nf = 0; nf < 12; nf++) {
                unsigned bfr[2] = { __float_as_uint(v0[nf]), __float_as_uint(v1[nf]) };
                mma8(accO[nf], afr, bfr);
            }
        }
    }

    // ---- epilogue ----
    float il_lo = 1.0f / l_lo, il_hi = 1.0f / l_hi;
    float* og_lo = g_att + (size_t)(b * Tn + q0 + qw + lr) * HV + h * Vn;
    float* og_hi = og_lo + (size_t)8 * HV;
#pragma unroll
    for (int nf = 0; nf < 12; nf++) {
        int cc = nhalf * 96 + nf * 8 + 2 * lc;
        *(float2*)(og_lo + cc) = make_float2(accO[nf][0] * il_lo, accO[nf][1] * il_lo);
        *(float2*)(og_hi + cc) = make_float2(accO[nf][2] * il_hi, accO[nf][3] * il_hi);
    }
}

// ---------------- host orchestration ------------------------------------------
extern "C" void kernel_launch(void* const* d_in, const int* in_sizes, int n_in,
                              void* d_out, int out_size)
{
    (void)in_sizes; (void)n_in; (void)out_size;
    const float* x    = (const float*)d_in[0];
    const float* Wq   = (const float*)d_in[1];
    const float* Wk   = (const float*)d_in[2];
    const float* Wv   = (const float*)d_in[3];
    const float* Wrk  = (const float*)d_in[4];
    const float* Wemb = (const float*)d_in[5];
    const float* rwb  = (const float*)d_in[6];
    const float* rrb  = (const float*)d_in[7];
    float* out = (float*)d_out;

    float *emb, *rkT, *q, *kT, *v, *att;
    cudaGetSymbolAddress((void**)&emb, g_emb);
    cudaGetSymbolAddress((void**)&rkT, g_rkT);
    cudaGetSymbolAddress((void**)&q,   g_q);
    cudaGetSymbolAddress((void**)&kT,  g_kT);
    cudaGetSymbolAddress((void**)&v,   g_v);
    cudaGetSymbolAddress((void**)&att, g_att);

    const int fa_smem = (64 * LDKC + 64 * LDRK + 64 * LDVC + 256) * 4;  // 130048 B
    cudaFuncSetAttribute(flash_kernel, cudaFuncAttributeMaxDynamicSharedMemorySize, fa_smem);

    // 1) positional features
    int n1 = Rn * 96;
    pos_fill<<<(n1 + 255) / 256, 256>>>();
    pos_max<<<1, 256>>>();
    pos_fin<<<(n1 + 255) / 256, 256>>>();

    // 2) r_kT = (emb @ Wrk)^T, tf32-rounded, ld 3072
    tgemm_kernel<<<dim3(4, 24, 1), 256>>>(emb, Wrk, rkT, Rn, HK, 192, 192, HK, 3072,
                                          1, 0, 0, 0, 0, 0, 0, 1.0f, 3);
    // 3) q = (x @ Wq) * K^-0.5 (fp32) ; kT = (x @ Wk)^T tf32 ; v = x @ Wv tf32
    tgemm_kernel<<<dim3(4, 24, 1), 256>>>(x, Wq, q, Bn * Tn, HK, Dn, Dn, HK, HK,
                                          1, 0, 0, 0, 0, 0, 0, 0.125f, 0);
    tgemm_kernel<<<dim3(4, 24, 1), 256>>>(x, Wk, kT, Bn * Tn, HK, Dn, Dn, HK, 3072,
                                          1, 0, 0, 0, 0, 0, 0, 1.0f, 3);
    tgemm_kernel<<<dim3(12, 24, 1), 256>>>(x, Wv, v, Bn * Tn, HV, Dn, Dn, HV, HV,
                                           1, 0, 0, 0, 0, 0, 0, 1.0f, 1);

    // 4) fused attention (logits + relative shift + softmax + PV)
    flash_kernel<<<dim3(24, 16), 256, fa_smem>>>(rwb, rrb);

    // 5) out = att @ Wemb
    tgemm_kernel<<<dim3(12, 24, 1), 256>>>(att, Wemb, out, Bn * Tn, Dn, HV,
                                           HV, Dn, Dn, 1, 0, 0, 0, 0, 0, 0, 1.0f, 0);
}

// round 6
// speedup vs baseline: 1.0242x; 1.0242x over previous
#include <cuda_runtime.h>
#include <math.h>

#define Bn 2
#define Tn 1536
#define Dn 1536
#define Hn 8
#define Kn 64
#define Vn 192
#define HK 512       // H*K
#define HV 1536      // H*V
#define Rn 3071      // 2T-1

// ---------------- scratch (device globals; no allocation allowed) -------------
__device__ float g_emb[(size_t)Rn * 192];
__device__ float g_gmax;
__device__ float g_rk[(size_t)Rn * HK];      // tf32-rounded
__device__ float g_q[(size_t)Bn * Tn * HK];  // tf32-rounded, scaled
__device__ float g_k[(size_t)Bn * Tn * HK];  // tf32-rounded
__device__ float g_v[(size_t)Bn * Tn * HV];  // tf32-rounded
__device__ float g_att[(size_t)Bn * Tn * HV];
__device__ float g_c1[8 * 3072];             // rwb.k  [h][b*T+t]
__device__ float g_c2[8 * 3072];             // rrb.rk [h][m]

// ---------------- tf32 helpers -------------------------------------------------
__device__ __forceinline__ unsigned f2tf(float x) {
    unsigned u; asm("cvt.rna.tf32.f32 %0, %1;" : "=r"(u) : "f"(x)); return u;
}
__device__ __forceinline__ void mma8(float d[4], const unsigned a[4], const unsigned b[2]) {
    asm volatile(
        "mma.sync.aligned.m16n8k8.row.col.f32.tf32.tf32.f32 "
        "{%0,%1,%2,%3}, {%4,%5,%6,%7}, {%8,%9}, {%0,%1,%2,%3};"
        : "+f"(d[0]), "+f"(d[1]), "+f"(d[2]), "+f"(d[3])
        : "r"(a[0]), "r"(a[1]), "r"(a[2]), "r"(a[3]), "r"(b[0]), "r"(b[1]));
}
#define CP16(dst_u32, src_ptr) \
    asm volatile("cp.async.cg.shared.global [%0], [%1], 16;" :: "r"(dst_u32), "l"(src_ptr))
#define CP_COMMIT() asm volatile("cp.async.commit_group;")
#define CP_WAIT0()  asm volatile("cp.async.wait_group 0;")
#define CP_WAIT1()  asm volatile("cp.async.wait_group 1;")

// ---------------- positional features ----------------------------------------
__global__ void pos_fill() {
    int idx = blockIdx.x * 256 + threadIdx.x;
    if (idx >= Rn * 96) return;
    int p = idx / 96, c = idx % 96;
    float ap = fabsf((float)(p - (Tn - 1)));
    float v;
    if (c < 32) {
        float max_range = log2f((float)Tn);
        float hl = exp2f(3.0f + (float)c * (max_range - 3.0f) / 31.0f);
        v = exp2f(-ap / hl);
    } else if (c < 64) {
        float w = exp2f((float)(c - 32 + 1)) - 1.0f;
        v = (w > ap) ? 1.0f : 0.0f;
    } else {
        int i = c - 64;
        float mean = 48.0f * (float)(i + 1);
        float conc = (mean / 24.0f) * (mean / 24.0f);
        float rate = mean * (1.0f / 576.0f);
        float lp = (conc - 1.0f) * logf(ap) - rate * ap
                   - (lgammaf(conc) - conc * logf(rate));
        v = expf(lp) + 1e-8f;
    }
    g_emb[(size_t)p * 192 + c] = v;
}

__global__ void pos_max() {
    __shared__ float red[256];
    int tid = threadIdx.x;
    float m = 0.0f;
    for (int idx = tid; idx < Rn * 32; idx += 256) {
        int p = idx >> 5, i = idx & 31;
        m = fmaxf(m, g_emb[(size_t)p * 192 + 64 + i]);
    }
    red[tid] = m;
    __syncthreads();
    for (int o = 128; o > 0; o >>= 1) {
        if (tid < o) red[tid] = fmaxf(red[tid], red[tid + o]);
        __syncthreads();
    }
    if (tid == 0) g_gmax = red[0];
}

__global__ void pos_fin() {
    int idx = blockIdx.x * 256 + threadIdx.x;
    if (idx >= Rn * 96) return;
    int p = idx / 96, c = idx % 96;
    float v = g_emb[(size_t)p * 192 + c];
    if (c >= 64) {
        v = v / g_gmax;
        g_emb[(size_t)p * 192 + c] = v;
    }
    float sgn = (p < Tn - 1) ? -1.0f : ((p > Tn - 1) ? 1.0f : 0.0f);
    g_emb[(size_t)p * 192 + 96 + c] = sgn * v;
}

// ---------------- rank-1 bias precompute ---------------------------------------
__global__ __launch_bounds__(64) void bias_kernel(
    const float* __restrict__ src, const float* __restrict__ bias,
    float* __restrict__ dst, int nrows)
{
    int row = blockIdx.x;
    if (row >= nrows) return;
    int t = threadIdx.x;
    int h = t >> 3, part = t & 7;
    const float* sp = src + (size_t)row * HK + h * 64 + part * 8;
    const float* bp = bias + h * 64 + part * 8;
    float s = 0.f;
#pragma unroll
    for (int i = 0; i < 8; i++) s = fmaf(bp[i], sp[i], s);
    s += __shfl_down_sync(0xffffffffu, s, 4, 8);
    s += __shfl_down_sync(0xffffffffu, s, 2, 8);
    s += __shfl_down_sync(0xffffffffu, s, 1, 8);
    if (part == 0) dst[h * 3072 + row] = s;
}

// ---------------- tf32 tensor-core GEMM: C = alpha * A @ B --------------------
__device__ __forceinline__ float cvtmode(float x, int mode) {
    return (mode & 1) ? __uint_as_float(f2tf(x)) : x;
}
__global__ __launch_bounds__(256) void tgemm_kernel(
    const float* __restrict__ A, const float* __restrict__ B, float* __restrict__ C,
    int M, int N, int Kd, int lda, int ldb, int ldc, int Hdim,
    long sAb, long sAh, long sBb, long sBh, long sCb, long sCh, float alpha, int mode)
{
    int z = blockIdx.z;
    int bb = z / Hdim, hh = z % Hdim;
    A += (size_t)bb * sAb + (size_t)hh * sAh;
    B += (size_t)bb * sBb + (size_t)hh * sBh;
    C += (size_t)bb * sCb + (size_t)hh * sCh;

    __shared__ unsigned As[128 * 36];
    __shared__ unsigned Bs[32 * 136];

    int tid = threadIdx.x;
    int bm = blockIdx.y * 128, bn = blockIdx.x * 128;
    int w = tid >> 5, lane = tid & 31;
    int wm = w & 1, wn = w >> 1;
    int lr = lane >> 2, lc = lane & 3;

    int arow0 = tid >> 3;
    int ac4   = (tid & 7) << 2;
    int bc4   = lane << 2;
    bool bvalid = (bn + bc4) < N;
    bool avalid[4];
#pragma unroll
    for (int it = 0; it < 4; it++) avalid[it] = (bm + arow0 + it * 32) < M;

    float4 av[4], bv[4];
    const float4 z4 = make_float4(0.f, 0.f, 0.f, 0.f);
#pragma unroll
    for (int it = 0; it < 4; it++) {
        av[it] = avalid[it] ? *(const float4*)(A + (size_t)(bm + arow0 + it * 32) * lda + ac4) : z4;
        bv[it] = bvalid ? *(const float4*)(B + (size_t)(it * 8 + w) * ldb + bn + bc4) : z4;
    }

    float acc[4][4][4] = {};

    for (int k0 = 0; k0 < Kd; k0 += 32) {
#pragma unroll
        for (int it = 0; it < 4; it++) {
            unsigned* ap = As + (arow0 + it * 32) * 36 + ac4;
            ap[0] = f2tf(av[it].x); ap[1] = f2tf(av[it].y);
            ap[2] = f2tf(av[it].z); ap[3] = f2tf(av[it].w);
            unsigned* bp = Bs + (it * 8 + w) * 136 + bc4;
            bp[0] = f2tf(bv[it].x); bp[1] = f2tf(bv[it].y);
            bp[2] = f2tf(bv[it].z); bp[3] = f2tf(bv[it].w);
        }
        __syncthreads();
        if (k0 + 32 < Kd) {
#pragma unroll
            for (int it = 0; it < 4; it++) {
                av[it] = avalid[it] ? *(const float4*)(A + (size_t)(bm + arow0 + it * 32) * lda + (k0 + 32) + ac4) : z4;
                bv[it] = bvalid ? *(const float4*)(B + (size_t)(k0 + 32 + it * 8 + w) * ldb + bn + bc4) : z4;
            }
        }
#pragma unroll
        for (int s = 0; s < 4; s++) {
            int kb = s * 8;
            unsigned afr[4][4];
#pragma unroll
            for (int i = 0; i < 4; i++) {
                int r = wm * 64 + i * 16 + lr;
                afr[i][0] = As[r * 36 + kb + lc];
                afr[i][1] = As[(r + 8) * 36 + kb + lc];
                afr[i][2] = As[r * 36 + kb + 4 + lc];
                afr[i][3] = As[(r + 8) * 36 + kb + 4 + lc];
            }
            unsigned bfr[4][2];
#pragma unroll
            for (int j = 0; j < 4; j++) {
                int cc = wn * 32 + j * 8 + lr;
                bfr[j][0] = Bs[(kb + lc) * 136 + cc];
                bfr[j][1] = Bs[(kb + 4 + lc) * 136 + cc];
            }
#pragma unroll
            for (int i = 0; i < 4; i++)
#pragma unroll
                for (int j = 0; j < 4; j++)
                    mma8(acc[i][j], afr[i], bfr[j]);
        }
        __syncthreads();
    }

#pragma unroll
    for (int i = 0; i < 4; i++) {
        int r0 = bm + wm * 64 + i * 16 + lr;
#pragma unroll
        for (int j = 0; j < 4; j++) {
            int c0 = bn + wn * 32 + j * 8 + lc * 2;
            if (c0 < N) {
                if (r0 < M)
                    *(float2*)(C + (size_t)r0 * ldc + c0) =
                        make_float2(cvtmode(alpha * acc[i][j][0], mode),
                                    cvtmode(alpha * acc[i][j][1], mode));
                if (r0 + 8 < M)
                    *(float2*)(C + (size_t)(r0 + 8) * ldc + c0) =
                        make_float2(cvtmode(alpha * acc[i][j][2], mode),
                                    cvtmode(alpha * acc[i][j][3], mode));
            }
        }
    }
}

// ---------------- fused flash attention, cp.async double-buffered -------------
#define LDK 68
#define LDV 200
#define LDR 132
#define OFF_K0  0
#define OFF_K1  4352
#define OFF_RK0 8704
#define OFF_RK1 17408
#define OFF_V   26112
#define OFF_REL 38912
#define OFF_PS  47360
#define OFF_RED 51712
#define SM_FLOATS 51968   // 207,872 bytes

__global__ __launch_bounds__(256, 1) void flash_kernel() {
    extern __shared__ float smf[];
    float* Vs  = smf + OFF_V;
    float* rel = smf + OFF_REL;
    float* Ps  = smf + OFF_PS;
    float* smx = smf + OFF_RED;        // [128]
    float* sms = smx + 128;            // [128]

    int bh = blockIdx.y, b = bh >> 3, h = bh & 7;
    int q0 = blockIdx.x * 64;
    int tid = threadIdx.x, w = tid >> 5, lane = tid & 31;
    int lr = lane >> 2, lc = lane & 3;
    int qw = (w >> 1) * 16;
    int nhalf = w & 1;

    // zero RK row 127 in both buffers (never touched by cp.async)
    if (tid < 68)  smf[OFF_RK0 + 127 * LDK + tid] = 0.f;
    if (tid >= 68 && tid < 136) smf[OFF_RK1 + 127 * LDK + tid - 68] = 0.f;

    // Q fragments (pre-rounded tf32 in g_q)
    const float* qg = g_q + (size_t)(b * Tn + q0) * HK + h * Kn;
    unsigned qf[8][4];
#pragma unroll
    for (int s = 0; s < 8; s++) {
        int c = s * 8 + lc;
        qf[s][0] = __float_as_uint(qg[(size_t)(qw + lr) * HK + c]);
        qf[s][1] = __float_as_uint(qg[(size_t)(qw + 8 + lr) * HK + c]);
        qf[s][2] = __float_as_uint(qg[(size_t)(qw + lr) * HK + c + 4]);
        qf[s][3] = __float_as_uint(qg[(size_t)(qw + 8 + lr) * HK + c + 4]);
    }

    const float* c1base = g_c1 + h * 3072 + b * Tn;
    const float* c2base = g_c2 + h * 3072;

    // cp.async issue helpers: 16B chunk per thread, 16 chunks per 64-float row
    auto issue_krk = [&](int jt, int buf) {
        int j0 = jt * 64;
        const float* kg = g_k + (size_t)(b * Tn + j0) * HK + h * Kn;
        float* kbase = smf + (buf ? OFF_K1 : OFF_K0);
#pragma unroll
        for (int it = 0; it < 4; it++) {               // 1024 chunks: full 64x64 K tile
            int f = it * 256 + tid;
            int row = f >> 4, c = (f & 15) << 2;
            unsigned kd = (unsigned)__cvta_generic_to_shared(kbase + row * LDK + c);
            CP16(kd, kg + (size_t)row * HK + c);
        }
        int mbase = 1472 + j0 - q0;
        const float* rg = g_rk + (size_t)mbase * HK + h * Kn;
        float* rbase = smf + (buf ? OFF_RK1 : OFF_RK0);
#pragma unroll
        for (int it = 0; it < 8; it++) {               // 2032 chunks: full 127x64 band
            int f = it * 256 + tid;
            if (f < 2032) {
                int row = f >> 4, c = (f & 15) << 2;
                unsigned rd = (unsigned)__cvta_generic_to_shared(rbase + row * LDK + c);
                CP16(rd, rg + (size_t)row * HK + c);
            }
        }
        CP_COMMIT();
    };
    auto issue_v = [&](int jt) {
        int j0 = jt * 64;
        const float* vg = g_v + (size_t)(b * Tn + j0) * HV + h * Vn;
#pragma unroll
        for (int it = 0; it < 12; it++) {              // 3072 chunks: full 64x192 V tile
            int f = it * 256 + tid;
            int row = f / 48, c = (f % 48) << 2;
            unsigned vd = (unsigned)__cvta_generic_to_shared(Vs + row * LDV + c);
            CP16(vd, vg + (size_t)row * HV + c);
        }
        CP_COMMIT();
    };

    issue_krk(0, 0);

    float accO[12][4] = {};
    float m_lo = -1e30f, m_hi = -1e30f, l_lo = 0.f, l_hi = 0.f;

    for (int jt = 0; jt < 24; jt++) {
        int j0 = jt * 64;
        int cur = jt & 1;
        float* Kc  = smf + (cur ? OFF_K1 : OFF_K0);
        float* RKc = smf + (cur ? OFF_RK1 : OFF_RK0);

        CP_WAIT0();            // K/RK[jt] complete
        __syncthreads();       // tiles visible; Vs/rel/Ps free

        issue_v(jt);                               // group: V[jt]
        if (jt < 23) issue_krk(jt + 1, cur ^ 1);   // group: K/RK[jt+1]

        // ---- QK MMAs: rel (64 cols/warp over 128-band) + content (32 cols/warp) ----
        float acc1[8][4] = {};
        float acc2[4][4] = {};
#pragma unroll
        for (int s = 0; s < 8; s++) {
            int kb = s * 8;
#pragma unroll
            for (int jf = 0; jf < 8; jf++) {
                int cc = nhalf * 64 + jf * 8 + lr;
                unsigned bfr[2];
                bfr[0] = __float_as_uint(RKc[cc * LDK + kb + lc]);
                bfr[1] = __float_as_uint(RKc[cc * LDK + kb + 4 + lc]);
                mma8(acc1[jf], qf[s], bfr);
            }
#pragma unroll
            for (int jf = 0; jf < 4; jf++) {
                int cc = nhalf * 32 + jf * 8 + lr;
                unsigned bfr[2];
                bfr[0] = __float_as_uint(Kc[cc * LDK + kb + lc]);
                bfr[1] = __float_as_uint(Kc[cc * LDK + kb + 4 + lc]);
                mma8(acc2[jf], qf[s], bfr);
            }
        }

        // ---- stage rel + c2 into dedicated buffer ----
        int mbase = 1472 + j0 - q0;
        const float* c2p = c2base + mbase;
#pragma unroll
        for (int jf = 0; jf < 8; jf++) {
            int ml = nhalf * 64 + jf * 8 + 2 * lc;
            float2 c2v = (ml < 127) ? *(const float2*)(c2p + ml) : make_float2(0.f, 0.f);
            *(float2*)&rel[(qw + lr) * LDR + ml] =
                make_float2(acc1[jf][0] + c2v.x, acc1[jf][1] + c2v.y);
            *(float2*)&rel[(qw + 8 + lr) * LDR + ml] =
                make_float2(acc1[jf][2] + c2v.x, acc1[jf][3] + c2v.y);
        }
        __syncthreads();

        // ---- logits = content + c1 + shifted rel; row max ----
        const float* c1p = c1base + j0;
        float lg[4][4];
        float mx_lo = -1e30f, mx_hi = -1e30f;
#pragma unroll
        for (int jf = 0; jf < 4; jf++) {
            int jl = nhalf * 32 + jf * 8 + 2 * lc;
            float2 c1v = *(const float2*)(c1p + jl);
            int mlo = 63 + jl - (qw + lr);
            int mhi = mlo - 8;
            lg[jf][0] = acc2[jf][0] + c1v.x + rel[(qw + lr) * LDR + mlo];
            lg[jf][1] = acc2[jf][1] + c1v.y + rel[(qw + lr) * LDR + mlo + 1];
            lg[jf][2] = acc2[jf][2] + c1v.x + rel[(qw + 8 + lr) * LDR + mhi];
            lg[jf][3] = acc2[jf][3] + c1v.y + rel[(qw + 8 + lr) * LDR + mhi + 1];
            mx_lo = fmaxf(mx_lo, fmaxf(lg[jf][0], lg[jf][1]));
            mx_hi = fmaxf(mx_hi, fmaxf(lg[jf][2], lg[jf][3]));
        }
        mx_lo = fmaxf(mx_lo, __shfl_xor_sync(0xffffffffu, mx_lo, 1));
        mx_lo = fmaxf(mx_lo, __shfl_xor_sync(0xffffffffu, mx_lo, 2));
        mx_hi = fmaxf(mx_hi, __shfl_xor_sync(0xffffffffu, mx_hi, 1));
        mx_hi = fmaxf(mx_hi, __shfl_xor_sync(0xffffffffu, mx_hi, 2));
        if (lc == 0) {
            smx[nhalf * 64 + qw + lr] = mx_lo;
            smx[nhalf * 64 + qw + 8 + lr] = mx_hi;
        }
        __syncthreads();
        mx_lo = fmaxf(mx_lo, smx[(1 - nhalf) * 64 + qw + lr]);
        mx_hi = fmaxf(mx_hi, smx[(1 - nhalf) * 64 + qw + 8 + lr]);

        // ---- online softmax ----
        float mn_lo = fmaxf(m_lo, mx_lo), mn_hi = fmaxf(m_hi, mx_hi);
        float sc_lo = __expf(m_lo - mn_lo), sc_hi = __expf(m_hi - mn_hi);
        m_lo = mn_lo; m_hi = mn_hi;
        float su_lo = 0.f, su_hi = 0.f;
        float pv[4][4];
#pragma unroll
        for (int jf = 0; jf < 4; jf++) {
            pv[jf][0] = __expf(lg[jf][0] - mn_lo);
            pv[jf][1] = __expf(lg[jf][1] - mn_lo);
            pv[jf][2] = __expf(lg[jf][2] - mn_hi);
            pv[jf][3] = __expf(lg[jf][3] - mn_hi);
            su_lo += pv[jf][0] + pv[jf][1];
            su_hi += pv[jf][2] + pv[jf][3];
        }
        su_lo += __shfl_xor_sync(0xffffffffu, su_lo, 1);
        su_lo += __shfl_xor_sync(0xffffffffu, su_lo, 2);
        su_hi += __shfl_xor_sync(0xffffffffu, su_hi, 1);
        su_hi += __shfl_xor_sync(0xffffffffu, su_hi, 2);
        if (lc == 0) {
            sms[nhalf * 64 + qw + lr] = su_lo;
            sms[nhalf * 64 + qw + 8 + lr] = su_hi;
        }
        // ---- stage P (tf32) ----
#pragma unroll
        for (int jf = 0; jf < 4; jf++) {
            int jl = nhalf * 32 + jf * 8 + 2 * lc;
            *(uint2*)&Ps[(qw + lr) * LDK + jl] =
                make_uint2(f2tf(pv[jf][0]), f2tf(pv[jf][1]));
            *(uint2*)&Ps[(qw + 8 + lr) * LDK + jl] =
                make_uint2(f2tf(pv[jf][2]), f2tf(pv[jf][3]));
        }
        if (jt < 23) { CP_WAIT1(); } else { CP_WAIT0(); }   // V[jt] complete
        __syncthreads();
        l_lo = l_lo * sc_lo + su_lo + sms[(1 - nhalf) * 64 + qw + lr];
        l_hi = l_hi * sc_hi + su_hi + sms[(1 - nhalf) * 64 + qw + 8 + lr];

        // ---- rescale O, O += P @ V ----
#pragma unroll
        for (int nf = 0; nf < 12; nf++) {
            accO[nf][0] *= sc_lo; accO[nf][1] *= sc_lo;
            accO[nf][2] *= sc_hi; accO[nf][3] *= sc_hi;
        }
#pragma unroll
        for (int s = 0; s < 8; s++) {
            int kb = s * 8;
            unsigned afr[4];
            afr[0] = __float_as_uint(Ps[(qw + lr) * LDK + kb + lc]);
            afr[1] = __float_as_uint(Ps[(qw + 8 + lr) * LDK + kb + lc]);
            afr[2] = __float_as_uint(Ps[(qw + lr) * LDK + kb + 4 + lc]);
            afr[3] = __float_as_uint(Ps[(qw + 8 + lr) * LDK + kb + 4 + lc]);
#pragma unroll
            for (int nf = 0; nf < 12; nf++) {
                int cc = nhalf * 96 + nf * 8 + lr;
                unsigned bfr[2];
                bfr[0] = __float_as_uint(Vs[(kb + lc) * LDV + cc]);
                bfr[1] = __float_as_uint(Vs[(kb + 4 + lc) * LDV + cc]);
                mma8(accO[nf], afr, bfr);
            }
        }
    }

    // ---- epilogue ----
    float il_lo = 1.0f / l_lo, il_hi = 1.0f / l_hi;
    float* og_lo = g_att + (size_t)(b * Tn + q0 + qw + lr) * HV + h * Vn;
    float* og_hi = og_lo + (size_t)8 * HV;
#pragma unroll
    for (int nf = 0; nf < 12; nf++) {
        int cc = nhalf * 96 + nf * 8 + 2 * lc;
        *(float2*)(og_lo + cc) = make_float2(accO[nf][0] * il_lo, accO[nf][1] * il_lo);
        *(float2*)(og_hi + cc) = make_float2(accO[nf][2] * il_hi, accO[nf][3] * il_hi);
    }
}

// ---------------- host orchestration ------------------------------------------
extern "C" void kernel_launch(void* const* d_in, const int* in_sizes, int n_in,
                              void* d_out, int out_size)
{
    (void)in_sizes; (void)n_in; (void)out_size;
    const float* x    = (const float*)d_in[0];
    const float* Wq   = (const float*)d_in[1];
    const float* Wk   = (const float*)d_in[2];
    const float* Wv   = (const float*)d_in[3];
    const float* Wrk  = (const float*)d_in[4];
    const float* Wemb = (const float*)d_in[5];
    const float* rwb  = (const float*)d_in[6];
    const float* rrb  = (const float*)d_in[7];
    float* out = (float*)d_out;

    float *emb, *rk, *q, *k, *v, *att, *c1, *c2;
    cudaGetSymbolAddress((void**)&emb, g_emb);
    cudaGetSymbolAddress((void**)&rk,  g_rk);
    cudaGetSymbolAddress((void**)&q,   g_q);
    cudaGetSymbolAddress((void**)&k,   g_k);
    cudaGetSymbolAddress((void**)&v,   g_v);
    cudaGetSymbolAddress((void**)&att, g_att);
    cudaGetSymbolAddress((void**)&c1,  g_c1);
    cudaGetSymbolAddress((void**)&c2,  g_c2);

    const int fa_smem = SM_FLOATS * 4;
    cudaFuncSetAttribute(flash_kernel, cudaFuncAttributeMaxDynamicSharedMemorySize, fa_smem);

    // 1) positional features
    int n1 = Rn * 96;
    pos_fill<<<(n1 + 255) / 256, 256>>>();
    pos_max<<<1, 256>>>();
    pos_fin<<<(n1 + 255) / 256, 256>>>();

    // 2) projections (all tf32-rounded outputs)
    tgemm_kernel<<<dim3(4, 24, 1), 256>>>(emb, Wrk, rk, Rn, HK, 192, 192, HK, HK,
                                          1, 0, 0, 0, 0, 0, 0, 1.0f, 1);
    tgemm_kernel<<<dim3(4, 24, 1), 256>>>(x, Wq, q, Bn * Tn, HK, Dn, Dn, HK, HK,
                                          1, 0, 0, 0, 0, 0, 0, 0.125f, 1);
    tgemm_kernel<<<dim3(4, 24, 1), 256>>>(x, Wk, k, Bn * Tn, HK, Dn, Dn, HK, HK,
                                          1, 0, 0, 0, 0, 0, 0, 1.0f, 1);
    tgemm_kernel<<<dim3(12, 24, 1), 256>>>(x, Wv, v, Bn * Tn, HV, Dn, Dn, HV, HV,
                                           1, 0, 0, 0, 0, 0, 0, 1.0f, 1);

    // 3) rank-1 bias terms
    bias_kernel<<<3072, 64>>>(k,  rwb, c1, 3072);
    bias_kernel<<<3071, 64>>>(rk, rrb, c2, 3071);

    // 4) fused attention
    flash_kernel<<<dim3(24, 16), 256, fa_smem>>>();

    // 5) out = att @ Wemb
    tgemm_kernel<<<dim3(12, 24, 1), 256>>>(att, Wemb, out, Bn * Tn, Dn, HV,
                                           HV, Dn, Dn, 1, 0, 0, 0, 0, 0, 0, 1.0f, 0);
}